// round 13
// baseline (speedup 1.0000x reference)
#include <cuda_runtime.h>
#include <cuda_bf16.h>
#include <math_constants.h>
#include <cstdint>

// ---------------- problem constants ----------------
#define NPTS 100000
#define DIM  512
#define NQ   2048
#define TOPK 5
#define T1   8                  // per-slice candidates kept (phase 1)
#define TM   128
#define TN   128
#define KCH  128                // K chunk (int8 elements = bytes)
#define NCHK (DIM / KCH)        // 4
#define SPLIT 18
#define SLICE 5632              // 44 tiles * 128;  18*5632 >= NPTS
#define NCAND (SPLIT * T1)      // 144 candidates per query
#define RS   144                // smem row stride bytes (128B data + 16B pad)
#define SZT  (128 * RS)         // 18432 bytes per (operand, buffer)

// smem byte offsets (phase-1 kernel)
#define OFF_SC   0                       // scores 64 x 132 f32 = 33792 (two passes)
#define OFF_X2S  33792                   // 128 f32
#define OFF_XS   34304                   // 128 f32 (point scales, per tile)
#define OFF_QS   34816                   // 128 f32 (query scales, once)
#define OFF_A    35328                   // 2 bufs
#define OFF_B    (OFF_A + 2 * SZT)       // 72192
#define SMEM_TOT (OFF_B + 2 * SZT)       // 109056 -> 2 CTAs/SM

// ---------------- scratch ----------------
__device__ float g_x2[NPTS];
__device__ float g_xs[NPTS];
__device__ float g_qs[NQ];
__device__ int   g_idx[(size_t)NQ * NCAND];
__device__ int8_t g_Qb[(size_t)NQ * DIM];
__device__ int8_t g_Xb[(size_t)NPTS * DIM];

// ---------------- helpers ----------------
__device__ __forceinline__ uint32_t smem_u32(const void* p) {
    uint32_t a;
    asm("{ .reg .u64 t; cvta.to.shared.u64 t, %1; cvt.u32.u64 %0, t; }" : "=r"(a) : "l"(p));
    return a;
}
__device__ __forceinline__ void cpa16(uint32_t dst, const void* src, int sz) {
    asm volatile("cp.async.cg.shared.global [%0], [%1], 16, %2;"
                 :: "r"(dst), "l"(src), "r"(sz) : "memory");
}
#define CP_COMMIT() asm volatile("cp.async.commit_group;" ::: "memory")
#define CP_WAIT0()  asm volatile("cp.async.wait_group 0;" ::: "memory")

#define LDSM4(R0, R1, R2, R3, ADDR)                                          \
    asm volatile("ldmatrix.sync.aligned.m8n8.x4.shared.b16 {%0,%1,%2,%3}, [%4];" \
                 : "=r"(R0), "=r"(R1), "=r"(R2), "=r"(R3) : "r"(ADDR))
// int8 IMMA: m16n8k32 s8*s8 -> s32 (2x MAC/instr vs bf16 k16)
#define MMAI8(C, A, B0, B1)                                                  \
    asm volatile("mma.sync.aligned.m16n8k32.row.col.s32.s8.s8.s32 "         \
                 "{%0,%1,%2,%3}, {%4,%5,%6,%7}, {%8,%9}, {%0,%1,%2,%3};"    \
                 : "+r"((C)[0]), "+r"((C)[1]), "+r"((C)[2]), "+r"((C)[3])   \
                 : "r"((A)[0]), "r"((A)[1]), "r"((A)[2]), "r"((A)[3]),      \
                   "r"(B0), "r"(B1))

template <int D>
__device__ __forceinline__ void topd_ins(float v, int n, float bv[D], int bi[D]) {
    if (v > bv[D - 1]) {
        bv[D - 1] = v; bi[D - 1] = n;
#pragma unroll
        for (int s = D - 1; s > 0; --s) {
            if (bv[s] > bv[s - 1]) {
                float tv = bv[s]; bv[s] = bv[s - 1]; bv[s - 1] = tv;
                int   ti = bi[s]; bi[s] = bi[s - 1]; bi[s - 1] = ti;
            }
        }
    }
}

// ---------------------------------------------------------------------------
// fp32 -> int8 per-row symmetric quantization (+ scale, + optional ||row||^2).
// One warp per row.
// ---------------------------------------------------------------------------
__global__ void quant_kernel(const float* __restrict__ src,
                             int8_t* __restrict__ dst,
                             float* __restrict__ scale,
                             float* __restrict__ x2, int nrows)
{
    int row = (blockIdx.x * blockDim.x + threadIdx.x) >> 5;
    int lane = threadIdx.x & 31;
    if (row >= nrows) return;
    const float4* srow = (const float4*)(src + (size_t)row * DIM);
    float4 v[4];
    float s = 0.f, ma = 0.f;
#pragma unroll
    for (int i = 0; i < 4; ++i) {
        v[i] = srow[lane + i * 32];
        s += v[i].x * v[i].x + v[i].y * v[i].y + v[i].z * v[i].z + v[i].w * v[i].w;
        ma = fmaxf(ma, fmaxf(fmaxf(fabsf(v[i].x), fabsf(v[i].y)),
                             fmaxf(fabsf(v[i].z), fabsf(v[i].w))));
    }
#pragma unroll
    for (int o = 16; o; o >>= 1) {
        s  += __shfl_xor_sync(0xffffffffu, s, o);
        ma  = fmaxf(ma, __shfl_xor_sync(0xffffffffu, ma, o));
    }
    float sc  = (ma > 0.f) ? ma * (1.f / 127.f) : 1.f;
    float inv = 1.f / sc;
    char4* drow = (char4*)(dst + (size_t)row * DIM);
#pragma unroll
    for (int i = 0; i < 4; ++i) {
        drow[lane + i * 32] = make_char4(
            (char)__float2int_rn(v[i].x * inv), (char)__float2int_rn(v[i].y * inv),
            (char)__float2int_rn(v[i].z * inv), (char)__float2int_rn(v[i].w * inv));
    }
    if (lane == 0) {
        scale[row] = sc;
        if (x2) x2[row] = s;
    }
}

// ---------------------------------------------------------------------------
// cp.async fill for one chunk (A + B int8 tiles, 128 rows x 128 B) into `buf`.
// ---------------------------------------------------------------------------
__device__ __forceinline__ void issue_loads(uint32_t sb, int buf, int qbase,
                                            int nTile, int c, int tid)
{
    const int koff = c * KCH;
#pragma unroll
    for (int i = 0; i < 4; ++i) {
        int idx = tid + i * 256;
        int row = idx >> 3, seg = idx & 7;
        const int8_t* s = g_Qb + (size_t)(qbase + row) * DIM + koff + seg * 16;
        cpa16(sb + OFF_A + buf * SZT + row * RS + seg * 16, s, 16);
    }
#pragma unroll
    for (int i = 0; i < 4; ++i) {
        int idx = tid + i * 256;
        int row = idx >> 3, seg = idx & 7;
        int xr = nTile + row;
        int ok = xr < NPTS;
        const int8_t* s = g_Xb + (size_t)(ok ? xr : 0) * DIM + koff + seg * 16;
        cpa16(sb + OFF_B + buf * SZT + row * RS + seg * 16, s, ok ? 16 : 0);
    }
}

// ---------------------------------------------------------------------------
// Phase 1: int8 IMMA approx-distance GEMM + per-slice top-8 candidates.
// grid = (16, SPLIT), 256 threads, 2 CTAs/SM.
// ---------------------------------------------------------------------------
__global__ __launch_bounds__(256, 2) void knn_main()
{
    extern __shared__ char sm[];
    const uint32_t sb = smem_u32(sm);
    float* Sc  = (float*)(sm + OFF_SC);
    float* x2s = (float*)(sm + OFF_X2S);
    float* xs  = (float*)(sm + OFF_XS);
    float* qs  = (float*)(sm + OFF_QS);

    const int tid = threadIdx.x, wid = tid >> 5, lane = tid & 31;
    const int m_off = (wid & 1) * 64;
    const int n_off = (wid >> 1) * 32;
    const int qbase  = blockIdx.x * TM;
    const int nStart = blockIdx.y * SLICE;
    const int nEnd   = min(nStart + SLICE, NPTS);

    const uint32_t aoff = (uint32_t)(m_off + (lane & 15)) * RS + ((lane >> 4) << 4);
    const uint32_t boff = (uint32_t)(n_off + (lane & 7) + ((lane >> 4) << 3)) * RS
                        + (((lane >> 3) & 1) << 4);

    float bv[T1]; int bi[T1];
#pragma unroll
    for (int s = 0; s < T1; ++s) { bv[s] = -CUDART_INF_F; bi[s] = 0; }

    // ---- prologue ----
    if (tid < 128) {
        int n = nStart + tid;
        x2s[tid] = (n < nEnd) ? g_x2[n] : 0.f;
        xs[tid]  = (n < nEnd) ? g_xs[n] : 0.f;
        qs[tid]  = g_qs[qbase + tid];
    }
    issue_loads(sb, 0, qbase, nStart, 0, tid);
    CP_COMMIT();
    CP_WAIT0();
    __syncthreads();

    int buf = 0;
#pragma unroll 1
    for (int nTile = nStart; nTile < nEnd; nTile += TN) {
        const int colLim = min(TN, nEnd - nTile);

        int acc[4][4][4];
#pragma unroll
        for (int mi = 0; mi < 4; ++mi)
#pragma unroll
            for (int ni = 0; ni < 4; ++ni)
#pragma unroll
                for (int r = 0; r < 4; ++r) acc[mi][ni][r] = 0;

#pragma unroll 1
        for (int c = 0; c < NCHK; ++c) {
            const bool inTile = (c + 1 < NCHK);
            const bool hasNext = inTile || (nTile + TN < nEnd);
            if (hasNext) {
                issue_loads(sb, buf ^ 1, qbase, inTile ? nTile : nTile + TN,
                            inTile ? c + 1 : 0, tid);
                CP_COMMIT();
            }

            const uint32_t sA = sb + OFF_A + buf * SZT;
            const uint32_t sB = sb + OFF_B + buf * SZT;
#pragma unroll
            for (int s = 0; s < 4; ++s) {           // four k32 steps per 128-K chunk
                uint32_t a[4][4], b[4][2];
#pragma unroll
                for (int mi = 0; mi < 4; ++mi) {
                    uint32_t adr = sA + aoff + mi * (16 * RS) + s * 32;
                    LDSM4(a[mi][0], a[mi][1], a[mi][2], a[mi][3], adr);
                }
#pragma unroll
                for (int nj = 0; nj < 2; ++nj) {
                    uint32_t adr = sB + boff + nj * (16 * RS) + s * 32;
                    uint32_t r0, r1, r2, r3;
                    LDSM4(r0, r1, r2, r3, adr);
                    b[2 * nj][0] = r0; b[2 * nj][1] = r1;
                    b[2 * nj + 1][0] = r2; b[2 * nj + 1][1] = r3;
                }
#pragma unroll
                for (int mi = 0; mi < 4; ++mi)
#pragma unroll
                    for (int ni = 0; ni < 4; ++ni)
                        MMAI8(acc[mi][ni], a[mi], b[ni][0], b[ni][1]);
            }

            if (hasNext) CP_WAIT0();
            __syncthreads();
            buf ^= 1;
        }

        // ---- epilogue, two passes over 64-row Sc ----
        const int rlo = lane >> 2;
        const int cl  = (lane & 3) * 2;
#pragma unroll 1
        for (int p = 0; p < 2; ++p) {
            if ((wid & 1) == p) {   // warps with m_off == p*64 write local rows 0..63
#pragma unroll
                for (int mi = 0; mi < 4; ++mi) {
                    float sq0 = 2.f * qs[m_off + mi * 16 + rlo];
                    float sq1 = 2.f * qs[m_off + mi * 16 + rlo + 8];
#pragma unroll
                    for (int ni = 0; ni < 4; ++ni) {
                        int col = n_off + ni * 8 + cl;
                        float2 x2p = *(float2*)&x2s[col];
                        float2 sxp = *(float2*)&xs[col];
                        int r0 = mi * 16 + rlo;
                        float2 v0 = make_float2(
                            fmaf((float)acc[mi][ni][0], sq0 * sxp.x, -x2p.x),
                            fmaf((float)acc[mi][ni][1], sq0 * sxp.y, -x2p.y));
                        float2 v1 = make_float2(
                            fmaf((float)acc[mi][ni][2], sq1 * sxp.x, -x2p.x),
                            fmaf((float)acc[mi][ni][3], sq1 * sxp.y, -x2p.y));
                        *(float2*)&Sc[r0 * 132 + col] = v0;
                        *(float2*)&Sc[(r0 + 8) * 132 + col] = v1;
                    }
                }
            }
            __syncthreads();
            if ((tid >> 6) == p && tid < 128) {
                const int lrow = tid & 63;
#pragma unroll 1
                for (int c = 0; c < colLim; c += 4) {
                    float4 v = *(float4*)&Sc[lrow * 132 + c];
                    topd_ins<T1>(v.x, nTile + c + 0, bv, bi);
                    topd_ins<T1>(v.y, nTile + c + 1, bv, bi);
                    topd_ins<T1>(v.z, nTile + c + 2, bv, bi);
                    topd_ins<T1>(v.w, nTile + c + 3, bv, bi);
                }
            }
            __syncthreads();
        }

        if (nTile + TN < nEnd && tid < 128) {
            int n = nTile + TN + tid;
            x2s[tid] = (n < nEnd) ? g_x2[n] : 0.f;
            xs[tid]  = (n < nEnd) ? g_xs[n] : 0.f;
        }
    }

    if (tid < 128) {
        int q = qbase + tid;
        size_t base = (size_t)q * NCAND + blockIdx.y * T1;
#pragma unroll
        for (int s = 0; s < T1; ++s) g_idx[base + s] = bi[s];
    }
}

// ---------------------------------------------------------------------------
// Phase 2: exact fp32 rescore of 144 candidates per query, top-5, vote.
// ---------------------------------------------------------------------------
__global__ __launch_bounds__(256, 4) void knn_rescore(
    const float* __restrict__ Qm, const float* __restrict__ X,
    const int* __restrict__ Y, float* __restrict__ out)
{
    __shared__ float qrow[DIM];
    __shared__ float cval[NCAND];
    __shared__ int   cidx[NCAND];

    const int q = blockIdx.x;
    const int tid = threadIdx.x, wid = tid >> 5, lane = tid & 31;

    if (tid < 128) *(float4*)&qrow[tid * 4] = *(const float4*)(Qm + (size_t)q * DIM + tid * 4);
    if (tid < NCAND) cidx[tid] = g_idx[(size_t)q * NCAND + tid];
    __syncthreads();

    for (int c = wid; c < NCAND; c += 8) {
        int n = cidx[c];
        const float4* xr = (const float4*)(X + (size_t)n * DIM);
        const float4* qr = (const float4*)qrow;
        float s = 0.f;
#pragma unroll
        for (int i = 0; i < DIM / 4 / 32; ++i) {
            float4 xv = xr[lane + i * 32];
            float4 qv = qr[lane + i * 32];
            s += xv.x * qv.x + xv.y * qv.y + xv.z * qv.z + xv.w * qv.w;
        }
#pragma unroll
        for (int o = 16; o; o >>= 1) s += __shfl_xor_sync(0xffffffffu, s, o);
        if (lane == 0) cval[c] = 2.f * s - g_x2[n];
    }
    __syncthreads();

    if (tid == 0) {
        float bv[TOPK]; int bi[TOPK];
#pragma unroll
        for (int s = 0; s < TOPK; ++s) { bv[s] = -CUDART_INF_F; bi[s] = 0; }
        for (int c = 0; c < NCAND; ++c) topd_ins<TOPK>(cval[c], cidx[c], bv, bi);
        float v = 0.f;
#pragma unroll
        for (int k = 0; k < TOPK; ++k) v += (float)Y[bi[k]];
        out[q * 2 + 0] = v * (1.0f / TOPK);
        out[q * 2 + 1] = 0.f;
    }
}

// ---------------------------------------------------------------------------
extern "C" void kernel_launch(void* const* d_in, const int* in_sizes, int n_in,
                              void* d_out, int out_size) {
    const float* Qm = (const float*)d_in[0];
    const float* X  = (const float*)d_in[1];
    const int*   Y  = (const int*)d_in[2];
    float* out = (float*)d_out;

    cudaFuncSetAttribute(knn_main, cudaFuncAttributeMaxDynamicSharedMemorySize, SMEM_TOT);

    int8_t *qb, *xb; float *x2p, *xsp, *qsp;
    cudaGetSymbolAddress((void**)&qb, g_Qb);
    cudaGetSymbolAddress((void**)&xb, g_Xb);
    cudaGetSymbolAddress((void**)&x2p, g_x2);
    cudaGetSymbolAddress((void**)&xsp, g_xs);
    cudaGetSymbolAddress((void**)&qsp, g_qs);

    quant_kernel<<<(NPTS + 7) / 8, 256>>>(X, xb, xsp, x2p, NPTS);
    quant_kernel<<<(NQ + 7) / 8, 256>>>(Qm, qb, qsp, nullptr, NQ);

    dim3 grid(NQ / TM, SPLIT);
    knn_main<<<grid, 256, SMEM_TOT>>>();

    knn_rescore<<<NQ, 256>>>(Qm, X, Y, out);
}

// round 14
// speedup vs baseline: 1.5073x; 1.5073x over previous
#include <cuda_runtime.h>
#include <cuda_bf16.h>
#include <math_constants.h>
#include <cstdint>

// ---------------- problem constants ----------------
#define NPTS 100000
#define DIM  512
#define NQ   2048
#define TOPK 5
#define T1   12                 // per-slice candidates kept (phase 1)
#define TM   128
#define TN   128
#define KCH  128                // K chunk (fp8 elements = bytes)
#define NCHK (DIM / KCH)        // 4
#define SPLIT 18
#define SLICE 5632              // 44 tiles * 128;  18*5632 >= NPTS
#define NCAND (SPLIT * T1)      // 216 candidates per query
#define RS   144                // smem row stride bytes (128B data + 16B pad)
#define SZT  (128 * RS)         // 18432 bytes per (operand, buffer)

// smem byte offsets (phase-1 kernel)
#define OFF_SC   0                       // scores 64 x 132 f32 = 33792 (two passes)
#define OFF_X2S  33792                   // 128 f32
#define OFF_XS   34304                   // 128 f32 (point scales, per tile)
#define OFF_QS   34816                   // 128 f32 (query scales, once)
#define OFF_A    35328                   // 2 bufs
#define OFF_B    (OFF_A + 2 * SZT)       // 72192
#define SMEM_TOT (OFF_B + 2 * SZT)       // 109056 -> 2 CTAs/SM

// ---------------- scratch ----------------
__device__ float g_x2[NPTS];
__device__ float g_xs[NPTS];
__device__ float g_qs[NQ];
__device__ int   g_idx[(size_t)NQ * NCAND];
__device__ uint8_t g_Qb[(size_t)NQ * DIM];
__device__ uint8_t g_Xb[(size_t)NPTS * DIM];

// ---------------- helpers ----------------
__device__ __forceinline__ uint32_t smem_u32(const void* p) {
    uint32_t a;
    asm("{ .reg .u64 t; cvta.to.shared.u64 t, %1; cvt.u32.u64 %0, t; }" : "=r"(a) : "l"(p));
    return a;
}
// pack two fp32 -> e4m3x2 (byte0 = e0, byte1 = e1)
__device__ __forceinline__ uint16_t pk_e4m3(float e0, float e1) {
    uint16_t r;
    asm("cvt.rn.satfinite.e4m3x2.f32 %0, %1, %2;" : "=h"(r) : "f"(e1), "f"(e0));
    return r;
}
__device__ __forceinline__ void cpa16(uint32_t dst, const void* src, int sz) {
    asm volatile("cp.async.cg.shared.global [%0], [%1], 16, %2;"
                 :: "r"(dst), "l"(src), "r"(sz) : "memory");
}
#define CP_COMMIT() asm volatile("cp.async.commit_group;" ::: "memory")
#define CP_WAIT0()  asm volatile("cp.async.wait_group 0;" ::: "memory")

#define LDSM4(R0, R1, R2, R3, ADDR)                                          \
    asm volatile("ldmatrix.sync.aligned.m8n8.x4.shared.b16 {%0,%1,%2,%3}, [%4];" \
                 : "=r"(R0), "=r"(R1), "=r"(R2), "=r"(R3) : "r"(ADDR))
// fp8 e4m3 MMA: m16n8k32, fp32 accum — 2x MACs/instr vs bf16 k16
#define MMAF8(C, A, B0, B1)                                                  \
    asm volatile("mma.sync.aligned.m16n8k32.row.col.f32.e4m3.e4m3.f32 "     \
                 "{%0,%1,%2,%3}, {%4,%5,%6,%7}, {%8,%9}, {%0,%1,%2,%3};"    \
                 : "+f"((C)[0]), "+f"((C)[1]), "+f"((C)[2]), "+f"((C)[3])   \
                 : "r"((A)[0]), "r"((A)[1]), "r"((A)[2]), "r"((A)[3]),      \
                   "r"(B0), "r"(B1))

template <int D>
__device__ __forceinline__ void topd_ins(float v, int n, float bv[D], int bi[D]) {
    if (v > bv[D - 1]) {
        bv[D - 1] = v; bi[D - 1] = n;
#pragma unroll
        for (int s = D - 1; s > 0; --s) {
            if (bv[s] > bv[s - 1]) {
                float tv = bv[s]; bv[s] = bv[s - 1]; bv[s - 1] = tv;
                int   ti = bi[s]; bi[s] = bi[s - 1]; bi[s - 1] = ti;
            }
        }
    }
}

// ---------------------------------------------------------------------------
// fp32 -> e4m3 per-row symmetric quantization (+ scale, + optional ||row||^2).
// One warp per row.
// ---------------------------------------------------------------------------
__global__ void quant_kernel(const float* __restrict__ src,
                             uint8_t* __restrict__ dst,
                             float* __restrict__ scale,
                             float* __restrict__ x2, int nrows)
{
    int row = (blockIdx.x * blockDim.x + threadIdx.x) >> 5;
    int lane = threadIdx.x & 31;
    if (row >= nrows) return;
    const float4* srow = (const float4*)(src + (size_t)row * DIM);
    float4 v[4];
    float s = 0.f, ma = 0.f;
#pragma unroll
    for (int i = 0; i < 4; ++i) {
        v[i] = srow[lane + i * 32];
        s += v[i].x * v[i].x + v[i].y * v[i].y + v[i].z * v[i].z + v[i].w * v[i].w;
        ma = fmaxf(ma, fmaxf(fmaxf(fabsf(v[i].x), fabsf(v[i].y)),
                             fmaxf(fabsf(v[i].z), fabsf(v[i].w))));
    }
#pragma unroll
    for (int o = 16; o; o >>= 1) {
        s  += __shfl_xor_sync(0xffffffffu, s, o);
        ma  = fmaxf(ma, __shfl_xor_sync(0xffffffffu, ma, o));
    }
    float sc  = (ma > 0.f) ? ma * (1.f / 448.f) : 1.f;
    float inv = 1.f / sc;
    uint32_t* drow = (uint32_t*)(dst + (size_t)row * DIM);
#pragma unroll
    for (int i = 0; i < 4; ++i) {
        uint32_t lo = pk_e4m3(v[i].x * inv, v[i].y * inv);
        uint32_t hi = pk_e4m3(v[i].z * inv, v[i].w * inv);
        drow[lane + i * 32] = lo | (hi << 16);
    }
    if (lane == 0) {
        scale[row] = sc;
        if (x2) x2[row] = s;
    }
}

// ---------------------------------------------------------------------------
// cp.async fill for one chunk (A + B fp8 tiles, 128 rows x 128 B) into `buf`.
// ---------------------------------------------------------------------------
__device__ __forceinline__ void issue_loads(uint32_t sb, int buf, int qbase,
                                            int nTile, int c, int tid)
{
    const int koff = c * KCH;
#pragma unroll
    for (int i = 0; i < 4; ++i) {
        int idx = tid + i * 256;
        int row = idx >> 3, seg = idx & 7;
        const uint8_t* s = g_Qb + (size_t)(qbase + row) * DIM + koff + seg * 16;
        cpa16(sb + OFF_A + buf * SZT + row * RS + seg * 16, s, 16);
    }
#pragma unroll
    for (int i = 0; i < 4; ++i) {
        int idx = tid + i * 256;
        int row = idx >> 3, seg = idx & 7;
        int xr = nTile + row;
        int ok = xr < NPTS;
        const uint8_t* s = g_Xb + (size_t)(ok ? xr : 0) * DIM + koff + seg * 16;
        cpa16(sb + OFF_B + buf * SZT + row * RS + seg * 16, s, ok ? 16 : 0);
    }
}

// ---------------------------------------------------------------------------
// Phase 1: fp8 e4m3 MMA approx-distance GEMM + per-slice top-12 candidates.
// grid = (16, SPLIT), 256 threads, 2 CTAs/SM.
// ---------------------------------------------------------------------------
__global__ __launch_bounds__(256, 2) void knn_main()
{
    extern __shared__ char sm[];
    const uint32_t sb = smem_u32(sm);
    float* Sc  = (float*)(sm + OFF_SC);
    float* x2s = (float*)(sm + OFF_X2S);
    float* xs  = (float*)(sm + OFF_XS);
    float* qs  = (float*)(sm + OFF_QS);

    const int tid = threadIdx.x, wid = tid >> 5, lane = tid & 31;
    const int m_off = (wid & 1) * 64;
    const int n_off = (wid >> 1) * 32;
    const int qbase  = blockIdx.x * TM;
    const int nStart = blockIdx.y * SLICE;
    const int nEnd   = min(nStart + SLICE, NPTS);

    const uint32_t aoff = (uint32_t)(m_off + (lane & 15)) * RS + ((lane >> 4) << 4);
    const uint32_t boff = (uint32_t)(n_off + (lane & 7) + ((lane >> 4) << 3)) * RS
                        + (((lane >> 3) & 1) << 4);

    float bv[T1]; int bi[T1];
#pragma unroll
    for (int s = 0; s < T1; ++s) { bv[s] = -CUDART_INF_F; bi[s] = 0; }

    // ---- prologue ----
    if (tid < 128) {
        int n = nStart + tid;
        x2s[tid] = (n < nEnd) ? g_x2[n] : 0.f;
        xs[tid]  = (n < nEnd) ? g_xs[n] : 0.f;
        qs[tid]  = g_qs[qbase + tid];
    }
    issue_loads(sb, 0, qbase, nStart, 0, tid);
    CP_COMMIT();
    CP_WAIT0();
    __syncthreads();

    int buf = 0;
#pragma unroll 1
    for (int nTile = nStart; nTile < nEnd; nTile += TN) {
        const int colLim = min(TN, nEnd - nTile);

        float acc[4][4][4];
#pragma unroll
        for (int mi = 0; mi < 4; ++mi)
#pragma unroll
            for (int ni = 0; ni < 4; ++ni)
#pragma unroll
                for (int r = 0; r < 4; ++r) acc[mi][ni][r] = 0.f;

#pragma unroll 1
        for (int c = 0; c < NCHK; ++c) {
            const bool inTile = (c + 1 < NCHK);
            const bool hasNext = inTile || (nTile + TN < nEnd);
            if (hasNext) {
                issue_loads(sb, buf ^ 1, qbase, inTile ? nTile : nTile + TN,
                            inTile ? c + 1 : 0, tid);
                CP_COMMIT();
            }

            const uint32_t sA = sb + OFF_A + buf * SZT;
            const uint32_t sB = sb + OFF_B + buf * SZT;
#pragma unroll
            for (int s = 0; s < 4; ++s) {           // four k32 steps per 128-K chunk
                uint32_t a[4][4], b[4][2];
#pragma unroll
                for (int mi = 0; mi < 4; ++mi) {
                    uint32_t adr = sA + aoff + mi * (16 * RS) + s * 32;
                    LDSM4(a[mi][0], a[mi][1], a[mi][2], a[mi][3], adr);
                }
#pragma unroll
                for (int nj = 0; nj < 2; ++nj) {
                    uint32_t adr = sB + boff + nj * (16 * RS) + s * 32;
                    uint32_t r0, r1, r2, r3;
                    LDSM4(r0, r1, r2, r3, adr);
                    b[2 * nj][0] = r0; b[2 * nj][1] = r1;
                    b[2 * nj + 1][0] = r2; b[2 * nj + 1][1] = r3;
                }
#pragma unroll
                for (int mi = 0; mi < 4; ++mi)
#pragma unroll
                    for (int ni = 0; ni < 4; ++ni)
                        MMAF8(acc[mi][ni], a[mi], b[ni][0], b[ni][1]);
            }

            if (hasNext) CP_WAIT0();
            __syncthreads();
            buf ^= 1;
        }

        // ---- epilogue, two passes over 64-row Sc ----
        const int rlo = lane >> 2;
        const int cl  = (lane & 3) * 2;
#pragma unroll 1
        for (int p = 0; p < 2; ++p) {
            if ((wid & 1) == p) {   // warps with m_off == p*64 write local rows 0..63
#pragma unroll
                for (int mi = 0; mi < 4; ++mi) {
                    float sq0 = 2.f * qs[m_off + mi * 16 + rlo];
                    float sq1 = 2.f * qs[m_off + mi * 16 + rlo + 8];
#pragma unroll
                    for (int ni = 0; ni < 4; ++ni) {
                        int col = n_off + ni * 8 + cl;
                        float2 x2p = *(float2*)&x2s[col];
                        float2 sxp = *(float2*)&xs[col];
                        int r0 = mi * 16 + rlo;
                        float2 v0 = make_float2(
                            fmaf(acc[mi][ni][0], sq0 * sxp.x, -x2p.x),
                            fmaf(acc[mi][ni][1], sq0 * sxp.y, -x2p.y));
                        float2 v1 = make_float2(
                            fmaf(acc[mi][ni][2], sq1 * sxp.x, -x2p.x),
                            fmaf(acc[mi][ni][3], sq1 * sxp.y, -x2p.y));
                        *(float2*)&Sc[r0 * 132 + col] = v0;
                        *(float2*)&Sc[(r0 + 8) * 132 + col] = v1;
                    }
                }
            }
            __syncthreads();
            if ((tid >> 6) == p && tid < 128) {
                const int lrow = tid & 63;
#pragma unroll 1
                for (int c = 0; c < colLim; c += 4) {
                    float4 v = *(float4*)&Sc[lrow * 132 + c];
                    topd_ins<T1>(v.x, nTile + c + 0, bv, bi);
                    topd_ins<T1>(v.y, nTile + c + 1, bv, bi);
                    topd_ins<T1>(v.z, nTile + c + 2, bv, bi);
                    topd_ins<T1>(v.w, nTile + c + 3, bv, bi);
                }
            }
            __syncthreads();
        }

        if (nTile + TN < nEnd && tid < 128) {
            int n = nTile + TN + tid;
            x2s[tid] = (n < nEnd) ? g_x2[n] : 0.f;
            xs[tid]  = (n < nEnd) ? g_xs[n] : 0.f;
        }
    }

    if (tid < 128) {
        int q = qbase + tid;
        size_t base = (size_t)q * NCAND + blockIdx.y * T1;
#pragma unroll
        for (int s = 0; s < T1; ++s) g_idx[base + s] = bi[s];
    }
}

// ---------------------------------------------------------------------------
// Phase 2: exact fp32 rescore of 216 candidates per query, top-5, vote.
// ---------------------------------------------------------------------------
__global__ __launch_bounds__(256, 4) void knn_rescore(
    const float* __restrict__ Qm, const float* __restrict__ X,
    const int* __restrict__ Y, float* __restrict__ out)
{
    __shared__ float qrow[DIM];
    __shared__ float cval[NCAND];
    __shared__ int   cidx[NCAND];

    const int q = blockIdx.x;
    const int tid = threadIdx.x, wid = tid >> 5, lane = tid & 31;

    if (tid < 128) *(float4*)&qrow[tid * 4] = *(const float4*)(Qm + (size_t)q * DIM + tid * 4);
    for (int i = tid; i < NCAND; i += 256) cidx[i] = g_idx[(size_t)q * NCAND + i];
    __syncthreads();

    for (int c = wid; c < NCAND; c += 8) {
        int n = cidx[c];
        const float4* xr = (const float4*)(X + (size_t)n * DIM);
        const float4* qr = (const float4*)qrow;
        float s = 0.f;
#pragma unroll
        for (int i = 0; i < DIM / 4 / 32; ++i) {
            float4 xv = xr[lane + i * 32];
            float4 qv = qr[lane + i * 32];
            s += xv.x * qv.x + xv.y * qv.y + xv.z * qv.z + xv.w * qv.w;
        }
#pragma unroll
        for (int o = 16; o; o >>= 1) s += __shfl_xor_sync(0xffffffffu, s, o);
        if (lane == 0) cval[c] = 2.f * s - g_x2[n];
    }
    __syncthreads();

    if (tid == 0) {
        float bv[TOPK]; int bi[TOPK];
#pragma unroll
        for (int s = 0; s < TOPK; ++s) { bv[s] = -CUDART_INF_F; bi[s] = 0; }
        for (int c = 0; c < NCAND; ++c) topd_ins<TOPK>(cval[c], cidx[c], bv, bi);
        float v = 0.f;
#pragma unroll
        for (int k = 0; k < TOPK; ++k) v += (float)Y[bi[k]];
        out[q * 2 + 0] = v * (1.0f / TOPK);
        out[q * 2 + 1] = 0.f;
    }
}

// ---------------------------------------------------------------------------
extern "C" void kernel_launch(void* const* d_in, const int* in_sizes, int n_in,
                              void* d_out, int out_size) {
    const float* Qm = (const float*)d_in[0];
    const float* X  = (const float*)d_in[1];
    const int*   Y  = (const int*)d_in[2];
    float* out = (float*)d_out;

    cudaFuncSetAttribute(knn_main, cudaFuncAttributeMaxDynamicSharedMemorySize, SMEM_TOT);

    uint8_t *qb, *xb; float *x2p, *xsp, *qsp;
    cudaGetSymbolAddress((void**)&qb, g_Qb);
    cudaGetSymbolAddress((void**)&xb, g_Xb);
    cudaGetSymbolAddress((void**)&x2p, g_x2);
    cudaGetSymbolAddress((void**)&xsp, g_xs);
    cudaGetSymbolAddress((void**)&qsp, g_qs);

    quant_kernel<<<(NPTS + 7) / 8, 256>>>(X, xb, xsp, x2p, NPTS);
    quant_kernel<<<(NQ + 7) / 8, 256>>>(Qm, qb, qsp, nullptr, NQ);

    dim3 grid(NQ / TM, SPLIT);
    knn_main<<<grid, 256, SMEM_TOT>>>();

    knn_rescore<<<NQ, 256>>>(Qm, X, Y, out);
}

// round 17
// speedup vs baseline: 2.0579x; 1.3653x over previous
#include <cuda_runtime.h>
#include <cuda_bf16.h>
#include <math_constants.h>
#include <cstdint>

// ---------------- problem constants ----------------
#define NPTS 100000
#define DIM  512
#define NQ   2048
#define TOPK 5
#define T1   8                  // per-slice candidates kept (phase 1)
#define TM   128
#define TN   128
#define KCH  64                 // K chunk (elements)
#define NCHK (DIM / KCH)        // 8
#define SPLIT 18
#define SLICE 5632              // 44 tiles * 128;  18*5632 >= NPTS
#define NCAND (SPLIT * T1)      // 144 candidates per query
#define RS   144                // smem row stride bytes (128B data + 16B pad)
#define SZT  (128 * RS)         // 18432 bytes per (operand, buffer)

// smem byte offsets (phase-1 kernel)
#define OFF_SC   0                       // scores 64 x 132 f32 = 33792 (two passes)
#define OFF_X2S  33792                   // 128 f32 (pad to 512)
#define OFF_A    34304                   // 2 bufs
#define OFF_B    (OFF_A + 2 * SZT)       // 71168
#define SMEM_TOT (OFF_B + 2 * SZT)       // 108032  -> 2 CTAs/SM

// ---------------- scratch ----------------
__device__ float g_x2[NPTS];
__device__ int   g_idx[(size_t)NQ * NCAND];
__device__ __nv_bfloat16 g_Qb[(size_t)NQ * DIM];
__device__ __nv_bfloat16 g_Xb[(size_t)NPTS * DIM];

// ---------------- helpers ----------------
__device__ __forceinline__ uint32_t smem_u32(const void* p) {
    uint32_t a;
    asm("{ .reg .u64 t; cvta.to.shared.u64 t, %1; cvt.u32.u64 %0, t; }" : "=r"(a) : "l"(p));
    return a;
}
__device__ __forceinline__ uint32_t pack2(float e0, float e1) {
    uint32_t r;
    asm("cvt.rn.bf16x2.f32 %0, %1, %2;" : "=r"(r) : "f"(e1), "f"(e0));
    return r;
}
__device__ __forceinline__ void cpa16(uint32_t dst, const void* src, int sz) {
    asm volatile("cp.async.cg.shared.global [%0], [%1], 16, %2;"
                 :: "r"(dst), "l"(src), "r"(sz) : "memory");
}
#define CP_COMMIT() asm volatile("cp.async.commit_group;" ::: "memory")
#define CP_WAIT0()  asm volatile("cp.async.wait_group 0;" ::: "memory")

#define LDSM4(R0, R1, R2, R3, ADDR)                                          \
    asm volatile("ldmatrix.sync.aligned.m8n8.x4.shared.b16 {%0,%1,%2,%3}, [%4];" \
                 : "=r"(R0), "=r"(R1), "=r"(R2), "=r"(R3) : "r"(ADDR))
#define MMA(C, A, B0, B1)                                                    \
    asm volatile("mma.sync.aligned.m16n8k16.row.col.f32.bf16.bf16.f32 "     \
                 "{%0,%1,%2,%3}, {%4,%5,%6,%7}, {%8,%9}, {%0,%1,%2,%3};"    \
                 : "+f"((C)[0]), "+f"((C)[1]), "+f"((C)[2]), "+f"((C)[3])   \
                 : "r"((A)[0]), "r"((A)[1]), "r"((A)[2]), "r"((A)[3]),      \
                   "r"(B0), "r"(B1))

template <int D>
__device__ __forceinline__ void topd_ins(float v, int n, float bv[D], int bi[D]) {
    if (v > bv[D - 1]) {
        bv[D - 1] = v; bi[D - 1] = n;
#pragma unroll
        for (int s = D - 1; s > 0; --s) {
            if (bv[s] > bv[s - 1]) {
                float tv = bv[s]; bv[s] = bv[s - 1]; bv[s - 1] = tv;
                int   ti = bi[s]; bi[s] = bi[s - 1]; bi[s - 1] = ti;
            }
        }
    }
}

// ---------------------------------------------------------------------------
// fp32 -> bf16 convert (+ optional ||row||^2). One warp per row.
// ---------------------------------------------------------------------------
__global__ void conv_kernel(const float* __restrict__ src,
                            __nv_bfloat16* __restrict__ dst,
                            float* __restrict__ x2, int nrows)
{
    int row = (blockIdx.x * blockDim.x + threadIdx.x) >> 5;
    int lane = threadIdx.x & 31;
    if (row >= nrows) return;
    const float4* srow = (const float4*)(src + (size_t)row * DIM);
    uint2* drow = (uint2*)(dst + (size_t)row * DIM);
    float s = 0.f;
#pragma unroll
    for (int i = 0; i < DIM / 4 / 32; ++i) {
        float4 v = srow[lane + i * 32];
        s += v.x * v.x + v.y * v.y + v.z * v.z + v.w * v.w;
        drow[lane + i * 32] = make_uint2(pack2(v.x, v.y), pack2(v.z, v.w));
    }
    if (x2) {
#pragma unroll
        for (int o = 16; o; o >>= 1) s += __shfl_xor_sync(0xffffffffu, s, o);
        if (lane == 0) x2[row] = s;
    }
}

// ---------------------------------------------------------------------------
// cp.async fill for one chunk (A + B bf16 tiles) into buffer `buf`.
// ---------------------------------------------------------------------------
__device__ __forceinline__ void issue_loads(uint32_t sb, int buf, int qbase,
                                            int nTile, int c, int tid)
{
    const int koff = c * KCH;
#pragma unroll
    for (int i = 0; i < 4; ++i) {
        int idx = tid + i * 256;
        int row = idx >> 3, seg = idx & 7;
        const __nv_bfloat16* s = g_Qb + (size_t)(qbase + row) * DIM + koff + seg * 8;
        cpa16(sb + OFF_A + buf * SZT + row * RS + seg * 16, s, 16);
    }
#pragma unroll
    for (int i = 0; i < 4; ++i) {
        int idx = tid + i * 256;
        int row = idx >> 3, seg = idx & 7;
        int xr = nTile + row;
        int ok = xr < NPTS;
        const __nv_bfloat16* s = g_Xb + (size_t)(ok ? xr : 0) * DIM + koff + seg * 8;
        cpa16(sb + OFF_B + buf * SZT + row * RS + seg * 16, s, ok ? 16 : 0);
    }
}

// ---------------------------------------------------------------------------
// Phase 1: bf16 HMMA approx-distance GEMM + per-slice top-8 candidates.
// grid = (16, SPLIT), 256 threads, 2 CTAs/SM.
// Scan: per tile, pass p in {0,1} covers query rows [p*64, p*64+64).
// 128 scanner threads per pass; scanner thread (set p, s=tid&127) owns
// (row = p*64 + (s&63), colhalf = s>>6) and keeps a persistent top-8.
// Final: both halves of each row merged in-kernel -> per-slice top-8.
// ---------------------------------------------------------------------------
__global__ __launch_bounds__(256, 2) void knn_main()
{
    extern __shared__ char sm[];
    const uint32_t sb = smem_u32(sm);
    float* Sc  = (float*)(sm + OFF_SC);
    float* x2s = (float*)(sm + OFF_X2S);

    const int tid = threadIdx.x, wid = tid >> 5, lane = tid & 31;
    const int m_off = (wid & 1) * 64;
    const int n_off = (wid >> 1) * 32;
    const int qbase  = blockIdx.x * TM;
    const int nStart = blockIdx.y * SLICE;
    const int nEnd   = min(nStart + SLICE, NPTS);

    // scanner identity (fixed for the whole kernel)
    const int sPass = tid >> 7;            // which pass this thread scans in
    const int sRow  = sPass * 64 + (tid & 63);   // query row it owns
    const int sCh   = (tid >> 6) & 1;      // column half [sCh*64, sCh*64+64)

    const uint32_t aoff = (uint32_t)(m_off + (lane & 15)) * RS + ((lane >> 4) << 4);
    const uint32_t boff = (uint32_t)(n_off + (lane & 7) + ((lane >> 4) << 3)) * RS
                        + (((lane >> 3) & 1) << 4);

    float bv[T1]; int bi[T1];
#pragma unroll
    for (int s = 0; s < T1; ++s) { bv[s] = -CUDART_INF_F; bi[s] = 0; }

    // ---- prologue ----
    if (tid < 128) {
        int n = nStart + tid;
        x2s[tid] = (n < nEnd) ? g_x2[n] : 0.f;
    }
    issue_loads(sb, 0, qbase, nStart, 0, tid);
    CP_COMMIT();
    CP_WAIT0();
    __syncthreads();

    int buf = 0;
#pragma unroll 1
    for (int nTile = nStart; nTile < nEnd; nTile += TN) {
        const int colLim = min(TN, nEnd - nTile);

        float acc[4][4][4];
#pragma unroll
        for (int mi = 0; mi < 4; ++mi)
#pragma unroll
            for (int ni = 0; ni < 4; ++ni)
#pragma unroll
                for (int r = 0; r < 4; ++r) acc[mi][ni][r] = 0.f;

#pragma unroll 1
        for (int c = 0; c < NCHK; ++c) {
            const bool inTile = (c + 1 < NCHK);
            const bool hasNext = inTile || (nTile + TN < nEnd);
            if (hasNext) {
                issue_loads(sb, buf ^ 1, qbase, inTile ? nTile : nTile + TN,
                            inTile ? c + 1 : 0, tid);
                CP_COMMIT();
            }

            const uint32_t sA = sb + OFF_A + buf * SZT;
            const uint32_t sB = sb + OFF_B + buf * SZT;
#pragma unroll
            for (int s = 0; s < 4; ++s) {           // four k16 steps per chunk
                uint32_t a[4][4], b[4][2];
#pragma unroll
                for (int mi = 0; mi < 4; ++mi) {
                    uint32_t adr = sA + aoff + mi * (16 * RS) + s * 32;
                    LDSM4(a[mi][0], a[mi][1], a[mi][2], a[mi][3], adr);
                }
#pragma unroll
                for (int nj = 0; nj < 2; ++nj) {
                    uint32_t adr = sB + boff + nj * (16 * RS) + s * 32;
                    uint32_t r0, r1, r2, r3;
                    LDSM4(r0, r1, r2, r3, adr);
                    b[2 * nj][0] = r0; b[2 * nj][1] = r1;
                    b[2 * nj + 1][0] = r2; b[2 * nj + 1][1] = r3;
                }
#pragma unroll
                for (int mi = 0; mi < 4; ++mi)
#pragma unroll
                    for (int ni = 0; ni < 4; ++ni)
                        MMA(acc[mi][ni], a[mi], b[ni][0], b[ni][1]);
            }

            if (hasNext) CP_WAIT0();
            __syncthreads();
            buf ^= 1;
        }

        // ---- epilogue, two passes over 64-row Sc; 128 scanners x 64 cols ----
        const int rlo = lane >> 2;
        const int cl  = (lane & 3) * 2;
#pragma unroll 1
        for (int p = 0; p < 2; ++p) {
            if ((wid & 1) == p) {   // warps with m_off == p*64 write local rows 0..63
#pragma unroll
                for (int mi = 0; mi < 4; ++mi) {
#pragma unroll
                    for (int ni = 0; ni < 4; ++ni) {
                        int col = n_off + ni * 8 + cl;
                        float2 x2p = *(float2*)&x2s[col];
                        int r0 = mi * 16 + rlo;
                        float2 v0 = make_float2(2.f * acc[mi][ni][0] - x2p.x,
                                                2.f * acc[mi][ni][1] - x2p.y);
                        float2 v1 = make_float2(2.f * acc[mi][ni][2] - x2p.x,
                                                2.f * acc[mi][ni][3] - x2p.y);
                        *(float2*)&Sc[r0 * 132 + col] = v0;
                        *(float2*)&Sc[(r0 + 8) * 132 + col] = v1;
                    }
                }
            }
            __syncthreads();
            if (sPass == p) {
                const int lrow = tid & 63;
                const int c0 = sCh * 64;
                const int cLim = min(c0 + 64, colLim);
#pragma unroll 1
                for (int c = c0; c < cLim; c += 4) {
                    float4 v = *(float4*)&Sc[lrow * 132 + c];
                    topd_ins<T1>(v.x, nTile + c + 0, bv, bi);
                    topd_ins<T1>(v.y, nTile + c + 1, bv, bi);
                    topd_ins<T1>(v.z, nTile + c + 2, bv, bi);
                    topd_ins<T1>(v.w, nTile + c + 3, bv, bi);
                }
            }
            __syncthreads();
        }

        if (nTile + TN < nEnd && tid < 128) {
            int n = nTile + TN + tid;
            x2s[tid] = (n < nEnd) ? g_x2[n] : 0.f;
        }
    }

    // ---- final merge: two column-half lists per row -> slice top-8 ----
    // Layout in Sc: [row][ch][slot] pairs (val, idx): 128*2*8*2 floats = 16KB.
    {
        float* mv = Sc;                         // values
        int*   mi = (int*)(Sc + 128 * 2 * T1);  // indices
        int slot = (sRow * 2 + sCh) * T1;
#pragma unroll
        for (int s = 0; s < T1; ++s) { mv[slot + s] = bv[s]; mi[slot + s] = bi[s]; }
    }
    __syncthreads();
    if (tid < 128) {
        float* mv = Sc;
        int*   mi = (int*)(Sc + 128 * 2 * T1);
        float fv[T1]; int fi[T1];
#pragma unroll
        for (int s = 0; s < T1; ++s) { fv[s] = -CUDART_INF_F; fi[s] = 0; }
        int base0 = tid * 2 * T1;
#pragma unroll
        for (int s = 0; s < 2 * T1; ++s) topd_ins<T1>(mv[base0 + s], mi[base0 + s], fv, fi);
        int q = qbase + tid;
        size_t gbase = (size_t)q * NCAND + blockIdx.y * T1;
#pragma unroll
        for (int s = 0; s < T1; ++s) g_idx[gbase + s] = fi[s];
    }
}

// ---------------------------------------------------------------------------
// Phase 2: exact fp32 rescore of 144 candidates per query, top-5, vote.
// ---------------------------------------------------------------------------
__global__ __launch_bounds__(256, 4) void knn_rescore(
    const float* __restrict__ Qm, const float* __restrict__ X,
    const int* __restrict__ Y, float* __restrict__ out)
{
    __shared__ float qrow[DIM];
    __shared__ float cval[NCAND];
    __shared__ int   cidx[NCAND];

    const int q = blockIdx.x;
    const int tid = threadIdx.x, wid = tid >> 5, lane = tid & 31;

    if (tid < 128) *(float4*)&qrow[tid * 4] = *(const float4*)(Qm + (size_t)q * DIM + tid * 4);
    for (int i = tid; i < NCAND; i += 256) cidx[i] = g_idx[(size_t)q * NCAND + i];
    __syncthreads();

    for (int c = wid; c < NCAND; c += 8) {
        int n = cidx[c];
        const float4* xr = (const float4*)(X + (size_t)n * DIM);
        const float4* qr = (const float4*)qrow;
        float s = 0.f;
#pragma unroll
        for (int i = 0; i < DIM / 4 / 32; ++i) {
            float4 xv = xr[lane + i * 32];
            float4 qv = qr[lane + i * 32];
            s += xv.x * qv.x + xv.y * qv.y + xv.z * qv.z + xv.w * qv.w;
        }
#pragma unroll
        for (int o = 16; o; o >>= 1) s += __shfl_xor_sync(0xffffffffu, s, o);
        if (lane == 0) cval[c] = 2.f * s - g_x2[n];
    }
    __syncthreads();

    if (tid == 0) {
        float bv[TOPK]; int bi[TOPK];
#pragma unroll
        for (int s = 0; s < TOPK; ++s) { bv[s] = -CUDART_INF_F; bi[s] = 0; }
        for (int c = 0; c < NCAND; ++c) topd_ins<TOPK>(cval[c], cidx[c], bv, bi);
        float v = 0.f;
#pragma unroll
        for (int k = 0; k < TOPK; ++k) v += (float)Y[bi[k]];
        out[q * 2 + 0] = v * (1.0f / TOPK);
        out[q * 2 + 1] = 0.f;
    }
}

// ---------------------------------------------------------------------------
extern "C" void kernel_launch(void* const* d_in, const int* in_sizes, int n_in,
                              void* d_out, int out_size) {
    const float* Qm = (const float*)d_in[0];
    const float* X  = (const float*)d_in[1];
    const int*   Y  = (const int*)d_in[2];
    float* out = (float*)d_out;

    cudaFuncSetAttribute(knn_main, cudaFuncAttributeMaxDynamicSharedMemorySize, SMEM_TOT);

    __nv_bfloat16 *qb, *xb; float* x2p;
    cudaGetSymbolAddress((void**)&qb, g_Qb);
    cudaGetSymbolAddress((void**)&xb, g_Xb);
    cudaGetSymbolAddress((void**)&x2p, g_x2);

    conv_kernel<<<(NPTS + 7) / 8, 256>>>(X, xb, x2p, NPTS);
    conv_kernel<<<(NQ + 7) / 8, 256>>>(Qm, qb, nullptr, NQ);

    dim3 grid(NQ / TM, SPLIT);
    knn_main<<<grid, 256, SMEM_TOT>>>();

    knn_rescore<<<NQ, 256>>>(Qm, X, Y, out);
}